// round 2
// baseline (speedup 1.0000x reference)
#include <cuda_runtime.h>
#include <math.h>

// Problem constants
#define BB     2
#define SEQ    2048
#define DIM    2048
#define HH     16
#define QLORA  512
#define KVLORA 512
#define DNOPE  128
#define DROPE  64
#define DV     128
#define DQK    192          // DNOPE + DROPE
#define DKV    256          // DNOPE + DV
#define BSROWS (BB*SEQ)     // 4096

// ---------------- scratch (device globals; allocation-free) ----------------
__device__ float g_qa  [(size_t)BSROWS*QLORA];
__device__ float g_qn  [(size_t)BSROWS*QLORA];
__device__ float g_q   [(size_t)BSROWS*HH*DQK];
__device__ float g_kva [(size_t)BSROWS*(KVLORA+DROPE)];
__device__ float g_kvn [(size_t)BSROWS*KVLORA];
__device__ float g_kvb [(size_t)BSROWS*HH*DKV];
__device__ float g_k   [(size_t)BSROWS*HH*DQK];
__device__ float g_sc  [(size_t)BB*HH*SEQ*SEQ];   // 536 MB
__device__ float g_ao  [(size_t)BSROWS*HH*DV];

// ---------------------------------------------------------------------------
// Generic batched SGEMM: C = alpha * A @ B (+bias), 128x128x8 tiles, 8x8/thread
// TRANSB=false: B is [K,N] row-major (ldb = row stride)
// TRANSB=true : B is [N,K] row-major (ldb = row stride)   (C = A @ B^T)
// CAUSAL=0: none
// CAUSAL=1: scores mode — C[r][c] = -1e9 where r < c; fully-masked tiles skip K loop
// CAUSAL=2: attn@V mode — K loop truncated to row0+BM (attn==0 above diagonal)
// batching: blockIdx.z -> (b = z/Hdiv, h = z%Hdiv); pointer offsets via strides
// ---------------------------------------------------------------------------
template<bool TRANSB, int CAUSAL>
__global__ __launch_bounds__(256)
void gemm_kernel(const float* __restrict__ A, const float* __restrict__ Bm,
                 const float* __restrict__ bias, float* __restrict__ C,
                 int M, int N, int K, int lda, int ldb, int ldc, float alpha,
                 int Hdiv,
                 long sAb, long sAh, long sBb, long sBh, long sCb, long sCh)
{
    const int BM = 128, BN = 128, BK = 8;
    __shared__ float As[BK][BM];
    __shared__ float Bs[BK][BN];

    const int bz = blockIdx.z;
    const int b  = bz / Hdiv;
    const int h  = bz % Hdiv;
    A  += (size_t)b * sAb + (size_t)h * sAh;
    Bm += (size_t)b * sBb + (size_t)h * sBh;
    C  += (size_t)b * sCb + (size_t)h * sCh;

    const int tid  = threadIdx.x;
    const int row0 = blockIdx.y * BM;
    const int col0 = blockIdx.x * BN;

    if (CAUSAL == 1 && (row0 + BM - 1) < col0) {
        // tile entirely above diagonal -> all masked
        for (int e = tid; e < BM * BN; e += 256) {
            int r = e >> 7, c = e & 127;
            if (row0 + r < M && col0 + c < N)
                C[(size_t)(row0 + r) * ldc + (col0 + c)] = -1e9f;
        }
        return;
    }

    float acc[8][8];
#pragma unroll
    for (int i = 0; i < 8; i++)
#pragma unroll
        for (int j = 0; j < 8; j++) acc[i][j] = 0.f;

    int Keff = K;
    if (CAUSAL == 2) { int cap = row0 + BM; if (cap < Keff) Keff = cap; }

    const int tx = tid & 15;    // 16 cols of threads
    const int ty = tid >> 4;    // 16 rows of threads

    for (int k0 = 0; k0 < Keff; k0 += BK) {
        // A tile -> As[k][m]   (128x8 elements, 4 per thread)
#pragma unroll
        for (int i = 0; i < 4; i++) {
            int e  = tid + i * 256;
            int m  = e >> 3, kk = e & 7;
            int gr = row0 + m, gk = k0 + kk;
            As[kk][m] = (gr < M && gk < K) ? A[(size_t)gr * lda + gk] : 0.f;
        }
        // B tile -> Bs[k][n]
#pragma unroll
        for (int i = 0; i < 4; i++) {
            int e = tid + i * 256;
            if (TRANSB) {
                int n  = e >> 3, kk = e & 7;
                int gn = col0 + n, gk = k0 + kk;
                Bs[kk][n] = (gn < N && gk < K) ? Bm[(size_t)gn * ldb + gk] : 0.f;
            } else {
                int kk = e >> 7, n = e & 127;
                int gk = k0 + kk, gn = col0 + n;
                Bs[kk][n] = (gk < K && gn < N) ? Bm[(size_t)gk * ldb + gn] : 0.f;
            }
        }
        __syncthreads();

#pragma unroll
        for (int kk = 0; kk < BK; kk++) {
            float a[8], bv[8];
#pragma unroll
            for (int i = 0; i < 8; i++) a[i]  = As[kk][ty * 8 + i];
#pragma unroll
            for (int j = 0; j < 8; j++) bv[j] = Bs[kk][tx * 8 + j];
#pragma unroll
            for (int i = 0; i < 8; i++)
#pragma unroll
                for (int j = 0; j < 8; j++)
                    acc[i][j] += a[i] * bv[j];
        }
        __syncthreads();
    }

#pragma unroll
    for (int i = 0; i < 8; i++) {
        int gr = row0 + ty * 8 + i;
        if (gr >= M) continue;
#pragma unroll
        for (int j = 0; j < 8; j++) {
            int gc = col0 + tx * 8 + j;
            if (gc >= N) continue;
            float v = acc[i][j] * alpha;
            if (bias) v += bias[gc];
            if (CAUSAL == 1 && gr < gc) v = -1e9f;
            C[(size_t)gr * ldc + gc] = v;
        }
    }
}

// ------------------------------ RMSNorm ------------------------------------
__global__ void rmsnorm_kernel(const float* __restrict__ in,
                               const float* __restrict__ w,
                               float* __restrict__ out,
                               int n, int in_stride, int out_stride)
{
    int row = blockIdx.x;
    const float* x = in + (size_t)row * in_stride;
    float* y = out + (size_t)row * out_stride;
    int tid = threadIdx.x;

    float ss = 0.f;
    for (int i = tid; i < n; i += blockDim.x) { float v = x[i]; ss += v * v; }
#pragma unroll
    for (int o = 16; o > 0; o >>= 1) ss += __shfl_xor_sync(0xffffffffu, ss, o);
    __shared__ float red[8];
    if ((tid & 31) == 0) red[tid >> 5] = ss;
    __syncthreads();
    if (tid == 0) {
        float v = 0.f;
        for (int wgi = 0; wgi < (int)(blockDim.x >> 5); wgi++) v += red[wgi];
        red[0] = v;
    }
    __syncthreads();
    float inv = rsqrtf(red[0] / (float)n + 1e-6f);
    for (int i = tid; i < n; i += blockDim.x) y[i] = x[i] * inv * w[i];
}

// -------------------------- RoPE on q_pe (in place) -------------------------
__global__ void rope_q_kernel(float* __restrict__ q,
                              const float* __restrict__ fcos,
                              const float* __restrict__ fsin)
{
    int idx = blockIdx.x * blockDim.x + threadIdx.x;
    const int HALF = DROPE / 2;                // 32
    int total = BSROWS * HH * HALF;
    if (idx >= total) return;
    int i  = idx % HALF;
    int hh = (idx / HALF) % HH;
    int bs = idx / (HALF * HH);
    int s  = bs % SEQ;
    float c  = fcos[s * HALF + i];
    float sn = fsin[s * HALF + i];
    float* p = q + (size_t)bs * (HH * DQK) + hh * DQK + DNOPE + 2 * i;
    float x0 = p[0], x1 = p[1];
    p[0] = x0 * c - x1 * sn;
    p[1] = x0 * sn + x1 * c;
}

// ---------------- build K = concat(k_nope, rope(k_pe) broadcast) ------------
__global__ void build_k_kernel(const float* __restrict__ kvb,
                               const float* __restrict__ kva,
                               const float* __restrict__ fcos,
                               const float* __restrict__ fsin,
                               float* __restrict__ kk)
{
    const int HALF  = DROPE / 2;               // 32
    const int UNITS = DNOPE + HALF;            // 160
    int idx = blockIdx.x * blockDim.x + threadIdx.x;
    int total = BSROWS * HH * UNITS;
    if (idx >= total) return;
    int u  = idx % UNITS;
    int hh = (idx / UNITS) % HH;
    int bs = idx / (UNITS * HH);
    int s  = bs % SEQ;
    float* krow = kk + (size_t)bs * (HH * DQK) + hh * DQK;
    if (u < DNOPE) {
        krow[u] = kvb[(size_t)bs * (HH * DKV) + hh * DKV + u];
    } else {
        int i = u - DNOPE;
        float c  = fcos[s * HALF + i];
        float sn = fsin[s * HALF + i];
        const float* kp = kva + (size_t)bs * (KVLORA + DROPE) + KVLORA;
        float x0 = kp[2 * i], x1 = kp[2 * i + 1];
        krow[DNOPE + 2 * i]     = x0 * c - x1 * sn;
        krow[DNOPE + 2 * i + 1] = x0 * sn + x1 * c;
    }
}

// ------------------------------ row softmax ---------------------------------
__global__ void softmax_kernel(float* __restrict__ scores)
{
    size_t row = blockIdx.x;
    float* p = scores + row * (size_t)SEQ;
    int tid = threadIdx.x;
    __shared__ float red[8];
    __shared__ float s_mx, s_sum;

    float mx = -1e30f;
    for (int i = tid; i < SEQ; i += 256) mx = fmaxf(mx, p[i]);
#pragma unroll
    for (int o = 16; o > 0; o >>= 1) mx = fmaxf(mx, __shfl_xor_sync(0xffffffffu, mx, o));
    if ((tid & 31) == 0) red[tid >> 5] = mx;
    __syncthreads();
    if (tid == 0) {
        float v = red[0];
        for (int w = 1; w < 8; w++) v = fmaxf(v, red[w]);
        s_mx = v;
    }
    __syncthreads();
    mx = s_mx;

    float sum = 0.f;
    for (int i = tid; i < SEQ; i += 256) {
        float e = expf(p[i] - mx);
        p[i] = e;
        sum += e;
    }
#pragma unroll
    for (int o = 16; o > 0; o >>= 1) sum += __shfl_xor_sync(0xffffffffu, sum, o);
    if ((tid & 31) == 0) red[tid >> 5] = sum;
    __syncthreads();
    if (tid == 0) {
        float v = 0.f;
        for (int w = 0; w < 8; w++) v += red[w];
        s_sum = v;
    }
    __syncthreads();
    float inv = 1.f / s_sum;
    for (int i = tid; i < SEQ; i += 256) p[i] *= inv;
}

// -----------------------------------------------------------------------------
extern "C" void kernel_launch(void* const* d_in, const int* in_sizes, int n_in,
                              void* d_out, int out_size)
{
    (void)in_sizes; (void)n_in; (void)out_size;
    const float* x        = (const float*)d_in[0];
    const float* wq_a_w   = (const float*)d_in[1];
    const float* wq_a_b   = (const float*)d_in[2];
    const float* q_norm_w = (const float*)d_in[3];
    const float* wq_b_w   = (const float*)d_in[4];
    const float* wkv_a_w  = (const float*)d_in[5];
    const float* wkv_a_b  = (const float*)d_in[6];
    const float* kv_norm_w= (const float*)d_in[7];
    const float* wkv_b_w  = (const float*)d_in[8];
    const float* wo_w     = (const float*)d_in[9];
    const float* fcos     = (const float*)d_in[10];
    const float* fsin     = (const float*)d_in[11];
    float* out = (float*)d_out;

    float *qa, *qn, *qbuf, *kva, *kvn, *kvb, *kmat, *sc, *ao;
    cudaGetSymbolAddress((void**)&qa,   g_qa);
    cudaGetSymbolAddress((void**)&qn,   g_qn);
    cudaGetSymbolAddress((void**)&qbuf, g_q);
    cudaGetSymbolAddress((void**)&kva,  g_kva);
    cudaGetSymbolAddress((void**)&kvn,  g_kvn);
    cudaGetSymbolAddress((void**)&kvb,  g_kvb);
    cudaGetSymbolAddress((void**)&kmat, g_k);
    cudaGetSymbolAddress((void**)&sc,   g_sc);
    cudaGetSymbolAddress((void**)&ao,   g_ao);

    const float scale = 1.0f / sqrtf((float)DQK);
    dim3 blk(256);

    // 1. q_a = x @ wq_a_w + b            [4096,512]
    gemm_kernel<false,0><<<dim3(4,32,1), blk>>>(
        x, wq_a_w, wq_a_b, qa,
        BSROWS, QLORA, DIM, DIM, QLORA, QLORA, 1.f, 1, 0,0,0,0,0,0);

    // 2. q_norm = rmsnorm(q_a)
    rmsnorm_kernel<<<BSROWS, 256>>>(qa, q_norm_w, qn, QLORA, QLORA, QLORA);

    // 3. q = q_norm @ wq_b_w             [4096,3072]
    gemm_kernel<false,0><<<dim3(24,32,1), blk>>>(
        qn, wq_b_w, nullptr, qbuf,
        BSROWS, HH*DQK, QLORA, QLORA, HH*DQK, HH*DQK, 1.f, 1, 0,0,0,0,0,0);

    // 4. kv_full = x @ wkv_a_w + b       [4096,576]
    gemm_kernel<false,0><<<dim3(5,32,1), blk>>>(
        x, wkv_a_w, wkv_a_b, kva,
        BSROWS, KVLORA+DROPE, DIM, DIM, KVLORA+DROPE, KVLORA+DROPE, 1.f, 1, 0,0,0,0,0,0);

    // 5. kv_norm = rmsnorm(kv_full[:,:512])
    rmsnorm_kernel<<<BSROWS, 256>>>(kva, kv_norm_w, kvn, KVLORA, KVLORA+DROPE, KVLORA);

    // 6. kv_b = kv_norm @ wkv_b_w        [4096,4096]
    gemm_kernel<false,0><<<dim3(32,32,1), blk>>>(
        kvn, wkv_b_w, nullptr, kvb,
        BSROWS, HH*DKV, KVLORA, KVLORA, HH*DKV, HH*DKV, 1.f, 1, 0,0,0,0,0,0);

    // 7. RoPE on q_pe (in place)
    {
        int tot = BSROWS * HH * (DROPE/2);
        rope_q_kernel<<<(tot + 255)/256, 256>>>(qbuf, fcos, fsin);
    }

    // 8. build K = [k_nope | rope(k_pe)]  [B,S,H,192]
    {
        int tot = BSROWS * HH * (DNOPE + DROPE/2);
        build_k_kernel<<<(tot + 255)/256, 256>>>(kvb, kva, fcos, fsin, kmat);
    }

    // 9. scores = scale * q @ k^T + causal   batch (b,h): [2048,2048], K=192
    gemm_kernel<true,1><<<dim3(16,16,BB*HH), blk>>>(
        qbuf, kmat, nullptr, sc,
        SEQ, SEQ, DQK,
        HH*DQK /*lda*/, HH*DQK /*ldb*/, SEQ /*ldc*/, scale,
        HH,
        (long)SEQ*HH*DQK, (long)DQK,          // A strides (b, h)
        (long)SEQ*HH*DQK, (long)DQK,          // B strides
        (long)HH*SEQ*SEQ, (long)SEQ*SEQ);     // C strides

    // 10. softmax over key dim
    softmax_kernel<<<BB*HH*SEQ, 256>>>(sc);

    // 11. attn_out = attn @ v   batch (b,h): [2048,128], K=2048 (causal-truncated)
    gemm_kernel<false,2><<<dim3(1,16,BB*HH), blk>>>(
        sc, kvb + DNOPE /* v offset within DKV row */, nullptr, ao,
        SEQ, DV, SEQ,
        SEQ /*lda*/, HH*DKV /*ldb*/, HH*DV /*ldc*/, 1.f,
        HH,
        (long)HH*SEQ*SEQ, (long)SEQ*SEQ,      // A strides
        (long)SEQ*HH*DKV, (long)DKV,          // B strides
        (long)SEQ*HH*DV,  (long)DV);          // C strides

    // 12. out = attn_out @ wo_w          [4096,2048]
    gemm_kernel<false,0><<<dim3(16,32,1), blk>>>(
        ao, wo_w, nullptr, out,
        BSROWS, DIM, HH*DV, HH*DV, DIM, DIM, 1.f, 1, 0,0,0,0,0,0);
}

// round 3
// speedup vs baseline: 2.5748x; 2.5748x over previous
#include <cuda_runtime.h>
#include <math.h>
#include <stdint.h>

// Problem constants
#define BB     2
#define SEQ    2048
#define DIM    2048
#define HH     16
#define QLORA  512
#define KVLORA 512
#define DNOPE  128
#define DROPE  64
#define DV     128
#define DQK    192          // DNOPE + DROPE
#define DKV    256          // DNOPE + DV
#define BSROWS (BB*SEQ)     // 4096

// ---------------- scratch (device globals; allocation-free) ----------------
__device__ float g_qa  [(size_t)BSROWS*QLORA];
__device__ float g_qn  [(size_t)BSROWS*QLORA];
__device__ float g_q   [(size_t)BSROWS*HH*DQK];
__device__ float g_kva [(size_t)BSROWS*(KVLORA+DROPE)];
__device__ float g_kvn [(size_t)BSROWS*KVLORA];
__device__ float g_kvb [(size_t)BSROWS*HH*DKV];
__device__ float g_k   [(size_t)BSROWS*HH*DQK];
__device__ float g_sc  [(size_t)BB*HH*SEQ*SEQ];   // 536 MB (lower-tri only written)
__device__ float g_ao  [(size_t)BSROWS*HH*DV];

// --------------------------- tf32 helpers ----------------------------------
__device__ __forceinline__ uint32_t f2tf32(float x) {
    uint32_t r;
    asm("cvt.rna.tf32.f32 %0, %1;" : "=r"(r) : "f"(x));
    return r;
}
__device__ __forceinline__ float f2tf32f(float x) {
    return __uint_as_float(f2tf32(x));
}
__device__ __forceinline__ void mma_tf32(float* c, const uint32_t* a,
                                         uint32_t b0, uint32_t b1) {
    asm volatile(
        "mma.sync.aligned.m16n8k8.row.col.f32.tf32.tf32.f32 "
        "{%0,%1,%2,%3}, {%4,%5,%6,%7}, {%8,%9}, {%0,%1,%2,%3};"
        : "+f"(c[0]), "+f"(c[1]), "+f"(c[2]), "+f"(c[3])
        : "r"(a[0]), "r"(a[1]), "r"(a[2]), "r"(a[3]), "r"(b0), "r"(b1));
}

// ---------------------------------------------------------------------------
// Batched TF32 tensor-core GEMM: C = alpha * A @ B (+bias)
// Tile 128x128x16, 256 threads = 8 warps in 4(M) x 2(N); warp tile 32x64.
// mma.sync.m16n8k8 tf32, fp32 accumulate. Double-buffered smem, reg staging.
// TRANSB=false: B is [K,N] row-major. TRANSB=true: B is [N,K] (C = A @ B^T).
// CAUSAL=1: scores mode — fully-masked tiles skipped entirely (no writes);
//           diagonal tiles write -1e9 above diag (never read downstream).
// CAUSAL=2: attn@V mode — K loop truncated to row0+BM.
// ---------------------------------------------------------------------------
template<bool TRANSB, int CAUSAL>
__global__ __launch_bounds__(256)
void gemm_tf32(const float* __restrict__ A, const float* __restrict__ Bm,
               const float* __restrict__ bias, float* __restrict__ C,
               int M, int N, int K, int lda, int ldb, int ldc, float alpha,
               int Hdiv,
               long sAb, long sAh, long sBb, long sBh, long sCb, long sCh)
{
    const int BM = 128, BN = 128, BK = 16;
    __shared__ float As[2][BK][BM + 4];
    __shared__ float Bs[2][BK][BN + 4];

    const int bz = blockIdx.z;
    const int b  = bz / Hdiv;
    const int h  = bz % Hdiv;
    A  += (size_t)b * sAb + (size_t)h * sAh;
    Bm += (size_t)b * sBb + (size_t)h * sBh;
    C  += (size_t)b * sCb + (size_t)h * sCh;

    const int tid  = threadIdx.x;
    const int warp = tid >> 5;
    const int lane = tid & 31;
    const int wm   = warp >> 1;     // 0..3
    const int wn   = warp & 1;      // 0..1
    const int gid  = lane >> 2;     // 0..7
    const int tg   = lane & 3;      // 0..3

    const int row0 = blockIdx.y * BM;
    const int col0 = blockIdx.x * BN;

    if (CAUSAL == 1 && (row0 + BM - 1) < col0) {
        return;   // fully masked: never written, never read downstream
    }

    int Keff = K;
    if (CAUSAL == 2) { int cap = row0 + BM; if (cap < Keff) Keff = cap; }
    const int nIter = (Keff + BK - 1) / BK;

    float acc[2][8][4];
#pragma unroll
    for (int mt = 0; mt < 2; mt++)
#pragma unroll
        for (int nt = 0; nt < 8; nt++)
#pragma unroll
            for (int r = 0; r < 4; r++) acc[mt][nt][r] = 0.f;

    float4 rA[2], rB[2];

    auto gloadA = [&](int k0) {
#pragma unroll
        for (int i = 0; i < 2; i++) {
            int id = tid * 2 + i;
            int m  = id >> 2, kq = id & 3;
            int gr = row0 + m, gk = k0 + kq * 4;
            rA[i] = make_float4(0.f, 0.f, 0.f, 0.f);
            if (gr < M && gk < K)
                rA[i] = *(const float4*)(A + (size_t)gr * lda + gk);
        }
    };
    auto gloadB = [&](int k0) {
#pragma unroll
        for (int i = 0; i < 2; i++) {
            rB[i] = make_float4(0.f, 0.f, 0.f, 0.f);
            if (TRANSB) {
                int id = tid * 2 + i;
                int n  = id >> 2, kq = id & 3;
                int gn = col0 + n, gk = k0 + kq * 4;
                if (gn < N && gk < K)
                    rB[i] = *(const float4*)(Bm + (size_t)gn * ldb + gk);
            } else {
                int id = tid * 2 + i;
                int kk = id >> 5, nq = id & 31;
                int gk = k0 + kk, gn = col0 + nq * 4;
                if (gk < K && gn < N)
                    rB[i] = *(const float4*)(Bm + (size_t)gk * ldb + gn);
            }
        }
    };
    auto stsA = [&](int s) {
#pragma unroll
        for (int i = 0; i < 2; i++) {
            int id = tid * 2 + i;
            int m  = id >> 2, kq = id & 3;
            As[s][kq * 4 + 0][m] = f2tf32f(rA[i].x);
            As[s][kq * 4 + 1][m] = f2tf32f(rA[i].y);
            As[s][kq * 4 + 2][m] = f2tf32f(rA[i].z);
            As[s][kq * 4 + 3][m] = f2tf32f(rA[i].w);
        }
    };
    auto stsB = [&](int s) {
#pragma unroll
        for (int i = 0; i < 2; i++) {
            if (TRANSB) {
                int id = tid * 2 + i;
                int n  = id >> 2, kq = id & 3;
                Bs[s][kq * 4 + 0][n] = f2tf32f(rB[i].x);
                Bs[s][kq * 4 + 1][n] = f2tf32f(rB[i].y);
                Bs[s][kq * 4 + 2][n] = f2tf32f(rB[i].z);
                Bs[s][kq * 4 + 3][n] = f2tf32f(rB[i].w);
            } else {
                int id = tid * 2 + i;
                int kk = id >> 5, nq = id & 31;
                float4 v = make_float4(f2tf32f(rB[i].x), f2tf32f(rB[i].y),
                                       f2tf32f(rB[i].z), f2tf32f(rB[i].w));
                *(float4*)&Bs[s][kk][nq * 4] = v;
            }
        }
    };

    // prologue
    gloadA(0); gloadB(0);
    stsA(0);   stsB(0);
    __syncthreads();

    for (int it = 0; it < nIter; it++) {
        const int s = it & 1;
        if (it + 1 < nIter) { gloadA((it + 1) * BK); gloadB((it + 1) * BK); }

        // compute on buffer s (two k8-steps)
#pragma unroll
        for (int ks = 0; ks < 2; ks++) {
            const int kb = ks * 8;
            uint32_t af[2][4];
#pragma unroll
            for (int mt = 0; mt < 2; mt++) {
                int mr = wm * 32 + mt * 16 + gid;
                af[mt][0] = __float_as_uint(As[s][kb + tg    ][mr    ]);
                af[mt][1] = __float_as_uint(As[s][kb + tg    ][mr + 8]);
                af[mt][2] = __float_as_uint(As[s][kb + tg + 4][mr    ]);
                af[mt][3] = __float_as_uint(As[s][kb + tg + 4][mr + 8]);
            }
#pragma unroll
            for (int nt = 0; nt < 8; nt++) {
                int nc = wn * 64 + nt * 8 + gid;
                uint32_t b0 = __float_as_uint(Bs[s][kb + tg    ][nc]);
                uint32_t b1 = __float_as_uint(Bs[s][kb + tg + 4][nc]);
                mma_tf32(acc[0][nt], af[0], b0, b1);
                mma_tf32(acc[1][nt], af[1], b0, b1);
            }
        }

        if (it + 1 < nIter) { stsA(s ^ 1); stsB(s ^ 1); }
        __syncthreads();
    }

    // epilogue
#pragma unroll
    for (int mt = 0; mt < 2; mt++) {
        int gr = row0 + wm * 32 + mt * 16 + gid;
#pragma unroll
        for (int nt = 0; nt < 8; nt++) {
            int gc = col0 + wn * 64 + nt * 8 + 2 * tg;
            if (gc >= N) continue;
            float bx = 0.f, by = 0.f;
            if (bias) { bx = bias[gc]; by = bias[gc + 1]; }
#pragma unroll
            for (int rr = 0; rr < 2; rr++) {
                int r = gr + rr * 8;
                if (r >= M) continue;
                float v0 = acc[mt][nt][rr * 2 + 0] * alpha + bx;
                float v1 = acc[mt][nt][rr * 2 + 1] * alpha + by;
                if (CAUSAL == 1) {
                    if (r < gc)     v0 = -1e9f;
                    if (r < gc + 1) v1 = -1e9f;
                }
                *(float2*)&C[(size_t)r * ldc + gc] = make_float2(v0, v1);
            }
        }
    }
}

// ------------------------------ RMSNorm ------------------------------------
__global__ void rmsnorm_kernel(const float* __restrict__ in,
                               const float* __restrict__ w,
                               float* __restrict__ out,
                               int n, int in_stride, int out_stride)
{
    int row = blockIdx.x;
    const float* x = in + (size_t)row * in_stride;
    float* y = out + (size_t)row * out_stride;
    int tid = threadIdx.x;

    float ss = 0.f;
    for (int i = tid; i < n; i += blockDim.x) { float v = x[i]; ss += v * v; }
#pragma unroll
    for (int o = 16; o > 0; o >>= 1) ss += __shfl_xor_sync(0xffffffffu, ss, o);
    __shared__ float red[8];
    if ((tid & 31) == 0) red[tid >> 5] = ss;
    __syncthreads();
    if (tid == 0) {
        float v = 0.f;
        for (int wgi = 0; wgi < (int)(blockDim.x >> 5); wgi++) v += red[wgi];
        red[0] = v;
    }
    __syncthreads();
    float inv = rsqrtf(red[0] / (float)n + 1e-6f);
    for (int i = tid; i < n; i += blockDim.x) y[i] = x[i] * inv * w[i];
}

// -------------------------- RoPE on q_pe (in place) -------------------------
__global__ void rope_q_kernel(float* __restrict__ q,
                              const float* __restrict__ fcos,
                              const float* __restrict__ fsin)
{
    int idx = blockIdx.x * blockDim.x + threadIdx.x;
    const int HALF = DROPE / 2;                // 32
    int total = BSROWS * HH * HALF;
    if (idx >= total) return;
    int i  = idx % HALF;
    int hh = (idx / HALF) % HH;
    int bs = idx / (HALF * HH);
    int s  = bs % SEQ;
    float c  = fcos[s * HALF + i];
    float sn = fsin[s * HALF + i];
    float* p = q + (size_t)bs * (HH * DQK) + hh * DQK + DNOPE + 2 * i;
    float x0 = p[0], x1 = p[1];
    p[0] = x0 * c - x1 * sn;
    p[1] = x0 * sn + x1 * c;
}

// ---------------- build K = concat(k_nope, rope(k_pe) broadcast) ------------
__global__ void build_k_kernel(const float* __restrict__ kvb,
                               const float* __restrict__ kva,
                               const float* __restrict__ fcos,
                               const float* __restrict__ fsin,
                               float* __restrict__ kk)
{
    const int HALF  = DROPE / 2;               // 32
    const int UNITS = DNOPE + HALF;            // 160
    int idx = blockIdx.x * blockDim.x + threadIdx.x;
    int total = BSROWS * HH * UNITS;
    if (idx >= total) return;
    int u  = idx % UNITS;
    int hh = (idx / UNITS) % HH;
    int bs = idx / (UNITS * HH);
    int s  = bs % SEQ;
    float* krow = kk + (size_t)bs * (HH * DQK) + hh * DQK;
    if (u < DNOPE) {
        krow[u] = kvb[(size_t)bs * (HH * DKV) + hh * DKV + u];
    } else {
        int i = u - DNOPE;
        float c  = fcos[s * HALF + i];
        float sn = fsin[s * HALF + i];
        const float* kp = kva + (size_t)bs * (KVLORA + DROPE) + KVLORA;
        float x0 = kp[2 * i], x1 = kp[2 * i + 1];
        krow[DNOPE + 2 * i]     = x0 * c - x1 * sn;
        krow[DNOPE + 2 * i + 1] = x0 * sn + x1 * c;
    }
}

// ------------------- row softmax (causal-aware, reg cached) -----------------
__global__ void softmax_kernel(float* __restrict__ scores)
{
    size_t row = blockIdx.x;
    int s = (int)(row % SEQ);
    int valid = s + 1;                          // entries [0, valid) are live
    float* p = scores + row * (size_t)SEQ;
    int tid = threadIdx.x;
    __shared__ float red[8];
    __shared__ float s_mx, s_sum;

    float v[8];
#pragma unroll
    for (int j = 0; j < 8; j++) {
        int i = tid + j * 256;
        v[j] = (i < valid) ? p[i] : -1e30f;
    }

    float mx = -1e30f;
#pragma unroll
    for (int j = 0; j < 8; j++) mx = fmaxf(mx, v[j]);
#pragma unroll
    for (int o = 16; o > 0; o >>= 1) mx = fmaxf(mx, __shfl_xor_sync(0xffffffffu, mx, o));
    if ((tid & 31) == 0) red[tid >> 5] = mx;
    __syncthreads();
    if (tid == 0) {
        float m = red[0];
        for (int w = 1; w < 8; w++) m = fmaxf(m, red[w]);
        s_mx = m;
    }
    __syncthreads();
    mx = s_mx;

    float sum = 0.f;
#pragma unroll
    for (int j = 0; j < 8; j++) {
        int i = tid + j * 256;
        float e = (i < valid) ? expf(v[j] - mx) : 0.f;
        v[j] = e;
        sum += e;
    }
#pragma unroll
    for (int o = 16; o > 0; o >>= 1) sum += __shfl_xor_sync(0xffffffffu, sum, o);
    if ((tid & 31) == 0) red[tid >> 5] = sum;
    __syncthreads();
    if (tid == 0) {
        float t = 0.f;
        for (int w = 0; w < 8; w++) t += red[w];
        s_sum = t;
    }
    __syncthreads();
    float inv = 1.f / s_sum;
#pragma unroll
    for (int j = 0; j < 8; j++) {
        int i = tid + j * 256;
        p[i] = v[j] * inv;                      // zero-fills above diagonal
    }
}

// -----------------------------------------------------------------------------
extern "C" void kernel_launch(void* const* d_in, const int* in_sizes, int n_in,
                              void* d_out, int out_size)
{
    (void)in_sizes; (void)n_in; (void)out_size;
    const float* x        = (const float*)d_in[0];
    const float* wq_a_w   = (const float*)d_in[1];
    const float* wq_a_b   = (const float*)d_in[2];
    const float* q_norm_w = (const float*)d_in[3];
    const float* wq_b_w   = (const float*)d_in[4];
    const float* wkv_a_w  = (const float*)d_in[5];
    const float* wkv_a_b  = (const float*)d_in[6];
    const float* kv_norm_w= (const float*)d_in[7];
    const float* wkv_b_w  = (const float*)d_in[8];
    const float* wo_w     = (const float*)d_in[9];
    const float* fcos     = (const float*)d_in[10];
    const float* fsin     = (const float*)d_in[11];
    float* out = (float*)d_out;

    float *qa, *qn, *qbuf, *kva, *kvn, *kvb, *kmat, *sc, *ao;
    cudaGetSymbolAddress((void**)&qa,   g_qa);
    cudaGetSymbolAddress((void**)&qn,   g_qn);
    cudaGetSymbolAddress((void**)&qbuf, g_q);
    cudaGetSymbolAddress((void**)&kva,  g_kva);
    cudaGetSymbolAddress((void**)&kvn,  g_kvn);
    cudaGetSymbolAddress((void**)&kvb,  g_kvb);
    cudaGetSymbolAddress((void**)&kmat, g_k);
    cudaGetSymbolAddress((void**)&sc,   g_sc);
    cudaGetSymbolAddress((void**)&ao,   g_ao);

    const float scale = 1.0f / sqrtf((float)DQK);
    dim3 blk(256);

    // 1. q_a = x @ wq_a_w + b            [4096,512] K=2048
    gemm_tf32<false,0><<<dim3(4,32,1), blk>>>(
        x, wq_a_w, wq_a_b, qa,
        BSROWS, QLORA, DIM, DIM, QLORA, QLORA, 1.f, 1, 0,0,0,0,0,0);

    // 2. q_norm = rmsnorm(q_a)
    rmsnorm_kernel<<<BSROWS, 256>>>(qa, q_norm_w, qn, QLORA, QLORA, QLORA);

    // 3. q = q_norm @ wq_b_w             [4096,3072] K=512
    gemm_tf32<false,0><<<dim3(24,32,1), blk>>>(
        qn, wq_b_w, nullptr, qbuf,
        BSROWS, HH*DQK, QLORA, QLORA, HH*DQK, HH*DQK, 1.f, 1, 0,0,0,0,0,0);

    // 4. kv_full = x @ wkv_a_w + b       [4096,576] K=2048
    gemm_tf32<false,0><<<dim3(5,32,1), blk>>>(
        x, wkv_a_w, wkv_a_b, kva,
        BSROWS, KVLORA+DROPE, DIM, DIM, KVLORA+DROPE, KVLORA+DROPE, 1.f, 1, 0,0,0,0,0,0);

    // 5. kv_norm = rmsnorm(kv_full[:,:512])
    rmsnorm_kernel<<<BSROWS, 256>>>(kva, kv_norm_w, kvn, KVLORA, KVLORA+DROPE, KVLORA);

    // 6. kv_b = kv_norm @ wkv_b_w        [4096,4096] K=512
    gemm_tf32<false,0><<<dim3(32,32,1), blk>>>(
        kvn, wkv_b_w, nullptr, kvb,
        BSROWS, HH*DKV, KVLORA, KVLORA, HH*DKV, HH*DKV, 1.f, 1, 0,0,0,0,0,0);

    // 7. RoPE on q_pe (in place)
    {
        int tot = BSROWS * HH * (DROPE/2);
        rope_q_kernel<<<(tot + 255)/256, 256>>>(qbuf, fcos, fsin);
    }

    // 8. build K = [k_nope | rope(k_pe)]  [B,S,H,192]
    {
        int tot = BSROWS * HH * (DNOPE + DROPE/2);
        build_k_kernel<<<(tot + 255)/256, 256>>>(kvb, kva, fcos, fsin, kmat);
    }

    // 9. scores = scale * q @ k^T (causal)  batch (b,h): [2048,2048], K=192
    gemm_tf32<true,1><<<dim3(16,16,BB*HH), blk>>>(
        qbuf, kmat, nullptr, sc,
        SEQ, SEQ, DQK,
        HH*DQK, HH*DQK, SEQ, scale,
        HH,
        (long)SEQ*HH*DQK, (long)DQK,
        (long)SEQ*HH*DQK, (long)DQK,
        (long)HH*SEQ*SEQ, (long)SEQ*SEQ);

    // 10. softmax over key dim (causal-aware)
    softmax_kernel<<<BB*HH*SEQ, 256>>>(sc);

    // 11. attn_out = attn @ v   batch (b,h): [2048,128], K truncated causally
    gemm_tf32<false,2><<<dim3(1,16,BB*HH), blk>>>(
        sc, kvb + DNOPE, nullptr, ao,
        SEQ, DV, SEQ,
        SEQ, HH*DKV, HH*DV, 1.f,
        HH,
        (long)HH*SEQ*SEQ, (long)SEQ*SEQ,
        (long)SEQ*HH*DKV, (long)DKV,
        (long)SEQ*HH*DV,  (long)DV);

    // 12. out = attn_out @ wo_w          [4096,2048] K=2048
    gemm_tf32<false,0><<<dim3(16,32,1), blk>>>(
        ao, wo_w, nullptr, out,
        BSROWS, DIM, HH*DV, HH*DV, DIM, DIM, 1.f, 1, 0,0,0,0,0,0);
}